// round 14
// baseline (speedup 1.0000x reference)
#include <cuda_runtime.h>
#include <cstdint>

#define N_NODES 100000
#define N_EDGES 1600000
#define IN_C    128
#define HID_C   128
#define OUT_C   64
#define MAXDEG  128

// ---------------- scratch: device globals (device-code references only) -----
__device__ int    g_is64;
__device__ int    g_cnt[N_NODES];                          // incoming-degree counter
__device__ int    g_bkt[(size_t)N_NODES * MAXDEG];         // fixed-capacity edge buckets
__device__ float4 g_h1  [(size_t)N_NODES * HID_C / 4];     // X @ W1
__device__ float4 g_agg1[(size_t)N_NODES * HID_C / 4];     // relu(conv1 out)
__device__ float4 g_h2  [(size_t)N_NODES * OUT_C / 4];     // agg1 @ W2

// ---------------- zero counters ----------------------------------------------
__global__ void zero_kernel() {
    int i = blockIdx.x * blockDim.x + threadIdx.x;
    if (i < N_NODES) g_cnt[i] = 0;
}

// ---------------- edge dtype sniff (int32 vs int64) --------------------------
// int64 little-endian: odd 32-bit words are high words == 0 (ids < 2^31).
__global__ void sniff_kernel(const unsigned* __restrict__ ei_raw) {
    int zeros = 0;
#pragma unroll
    for (int k = 0; k < 64; k++)
        if (ei_raw[2 * k + 1] == 0u) zeros++;
    g_is64 = (zeros == 64) ? 1 : 0;
}

__device__ __forceinline__ int edge_row(const void* ei, int e) {
    return g_is64 ? (int)((const long long*)ei)[e] : ((const int*)ei)[e];
}
__device__ __forceinline__ int edge_col(const void* ei, int e) {
    return g_is64 ? (int)((const long long*)ei)[N_EDGES + e]
                  : ((const int*)ei)[N_EDGES + e];
}

// ---------------- bucket fill -------------------------------------------------
__global__ void fill_kernel(const void* __restrict__ ei) {
    int e = blockIdx.x * blockDim.x + threadIdx.x;
    if (e < N_EDGES) {
        int r = edge_row(ei, e);
        int c = edge_col(ei, e);
        if ((unsigned)c < (unsigned)N_NODES) {
            int pos = atomicAdd(&g_cnt[c], 1);       // true degree keeps counting
            if (pos < MAXDEG) {
                int rr = ((unsigned)r < (unsigned)N_NODES) ? r : 0;
                g_bkt[(size_t)c * MAXDEG + pos] = rr;
            }
        }
    }
}

// ---------------- packed f32x2 FMA --------------------------------------------
#define FMA_F32X2(d, a, b) \
    asm("fma.rn.f32x2 %0, %1, %2, %0;" : "+l"(d) : "l"(a), "l"(b))

// ---------------- double-buffered SGEMM, FFMA2, duplicated-A smem -------------
// A [M,128] row-major, W [128,BN] row-major. H = A @ W (pure).
// A tile stored DUPLICATED in smem ({a,a} pairs) so the inner loop needs no
// register packing: 6x LDS.128 + 32x FFMA2 per kk, zero MOVs.
template<int BN, int NT>
__device__ __forceinline__ void gemm_body(const float* __restrict__ A,
                                          const float* __restrict__ W,
                                          float* __restrict__ H) {
    constexpr int BM = 128, BK = 16, TM = 8, TN = 8, K = 128, KT = K / BK; // 8
    constexpr int TCOLS = BN / TN;                 // 16 (BN=128) or 8 (BN=64)
    constexpr int LA = (BM * BK) / (NT * 4);       // 2 (NT=256) or 4 (NT=128)
    constexpr int LB = (BK * BN) / (NT * 4);       // 2 (both)

    __shared__ float AsD[2][BK][2 * BM];           // duplicated A: [2m]=[2m+1]=a_m
    __shared__ float Bs [2][BK][BN];

    const int tid  = threadIdx.x;
    const int tRow = tid / TCOLS;
    const int tCol = tid % TCOLS;
    const int m0   = blockIdx.x * BM;

    unsigned long long acc2[TM][TN / 2];
#pragma unroll
    for (int i = 0; i < TM; i++)
#pragma unroll
        for (int j = 0; j < TN / 2; j++) acc2[i][j] = 0ull;

    float4 rA[LA], rB[LB];

#define G_LDG(k0)                                                             \
    {                                                                         \
        _Pragma("unroll")                                                     \
        for (int i = 0; i < LA; i++) {                                        \
            int idx = tid + i * NT;              /* float4 slot */            \
            int ar  = idx >> 2;                  /* 4 float4 per 16-f row */  \
            int ak  = (idx & 3) * 4;                                          \
            int m   = m0 + ar;                                                \
            rA[i] = (m < N_NODES)                                             \
                  ? *(const float4*)(A + (size_t)m * K + (k0) + ak)           \
                  : make_float4(0.f, 0.f, 0.f, 0.f);                          \
        }                                                                     \
        _Pragma("unroll")                                                     \
        for (int i = 0; i < LB; i++) {                                        \
            int idx = tid + i * NT;                                           \
            int bk  = idx / (BN / 4);                                         \
            int bn  = (idx % (BN / 4)) * 4;                                   \
            rB[i] = *(const float4*)(W + (size_t)((k0) + bk) * BN + bn);      \
        }                                                                     \
    }

#define G_STS(buf)                                                            \
    {                                                                         \
        _Pragma("unroll")                                                     \
        for (int i = 0; i < LA; i++) {                                        \
            int idx = tid + i * NT;                                           \
            int ar  = idx >> 2;                                               \
            int ak  = (idx & 3) * 4;                                          \
            *(float2*)&AsD[buf][ak + 0][2 * ar] = make_float2(rA[i].x, rA[i].x); \
            *(float2*)&AsD[buf][ak + 1][2 * ar] = make_float2(rA[i].y, rA[i].y); \
            *(float2*)&AsD[buf][ak + 2][2 * ar] = make_float2(rA[i].z, rA[i].z); \
            *(float2*)&AsD[buf][ak + 3][2 * ar] = make_float2(rA[i].w, rA[i].w); \
        }                                                                     \
        _Pragma("unroll")                                                     \
        for (int i = 0; i < LB; i++) {                                        \
            int idx = tid + i * NT;                                           \
            int bk  = idx / (BN / 4);                                         \
            int bn  = (idx % (BN / 4)) * 4;                                   \
            *(float4*)&Bs[buf][bk][bn] = rB[i];                               \
        }                                                                     \
    }

    G_LDG(0)
    G_STS(0)
    __syncthreads();

#pragma unroll 2
    for (int kt = 0; kt < KT; kt++) {
        const int buf = kt & 1;
        if (kt + 1 < KT) G_LDG((kt + 1) * BK)

#pragma unroll
        for (int kk = 0; kk < BK; kk++) {
            // A: 8 contiguous {a,a} ull pairs -> 4x LDS.128
            unsigned long long a2[TM];
            const unsigned long long* ap =
                (const unsigned long long*)&AsD[buf][kk][0];
#pragma unroll
            for (int i = 0; i < TM; i++) a2[i] = ap[tRow * TM + i];
            // B: 4 contiguous {b2j,b2j+1} ull pairs -> 2x LDS.128
            unsigned long long b2[TN / 2];
            const unsigned long long* bp =
                (const unsigned long long*)&Bs[buf][kk][0];
#pragma unroll
            for (int j = 0; j < TN / 2; j++) b2[j] = bp[tCol * (TN / 2) + j];
#pragma unroll
            for (int i = 0; i < TM; i++)
#pragma unroll
                for (int j = 0; j < TN / 2; j++)
                    FMA_F32X2(acc2[i][j], a2[i], b2[j]);
        }

        if (kt + 1 < KT) {
            G_STS(buf ^ 1)
            __syncthreads();
        }
    }
#undef G_LDG
#undef G_STS

#pragma unroll
    for (int i = 0; i < TM; i++) {
        int m = m0 + tRow * TM + i;
        if (m >= N_NODES) continue;
#pragma unroll
        for (int j = 0; j < TN / 2; j += 2) {
            int n = tCol * TN + j * 2;
            float2 p0 = *(float2*)&acc2[i][j];
            float2 p1 = *(float2*)&acc2[i][j + 1];
            float4 h = make_float4(p0.x, p0.y, p1.x, p1.y);
            *(float4*)(H + (size_t)m * BN + n) = h;
        }
    }
}

__global__ __launch_bounds__(256, 2)
void gemm1_kernel(const float* __restrict__ A, const float* __restrict__ W) {
    gemm_body<128, 256>(A, W, (float*)g_h1);
}

// A = g_agg1 (already relu'd by gather1)
__global__ __launch_bounds__(128, 4)
void gemm2_kernel(const float* __restrict__ W) {
    gemm_body<64, 128>((const float*)g_agg1, W, (float*)g_h2);
}

// ---------------- per-node gather over buckets (no atomics) -----------------
// LPN lanes per node; each lane owns one float4 column slot.
// OUT[c] = [relu]( H[c]*dinv[c]^2 + bias + sum_{(r,c)} dinv[r]*dinv[c]*H[r] )
template<int LPN, bool RELU_OUT>
__device__ __forceinline__ void gather_body(const float4* __restrict__ H,
                                            const float*  __restrict__ bias,
                                            float4* __restrict__ OUT) {
    int gtid = blockIdx.x * blockDim.x + threadIdx.x;
    int node = gtid / LPN;
    int lane = gtid % LPN;
    if (node >= N_NODES) return;

    int   cnt_true = g_cnt[node];
    int   cnt      = min(cnt_true, MAXDEG);
    float dc       = rsqrtf((float)cnt_true + 1.0f);

    const size_t base = (size_t)node * LPN + lane;

    // self-loop + bias
    float4 hs = H[base];
    float4 bi = *(const float4*)(bias + lane * 4);
    float  d2 = dc * dc;
    float4 acc = make_float4(fmaf(hs.x, d2, bi.x), fmaf(hs.y, d2, bi.y),
                             fmaf(hs.z, d2, bi.z), fmaf(hs.w, d2, bi.w));

    const int* bkt = &g_bkt[(size_t)node * MAXDEG];
    for (int j0 = 0; j0 < cnt; j0 += LPN) {
        int nb = min(LPN, cnt - j0);
        // one bucket entry per lane; dinv recomputed from counts (L2-hot)
        int   r_l = 0;
        float n_l = 0.0f;
        if (lane < nb) {
            r_l = bkt[j0 + lane];
            n_l = rsqrtf((float)g_cnt[r_l] + 1.0f);
        }
        for (int k = 0; k < nb; k++) {
            int   r  = __shfl_sync(0xffffffffu, r_l, k, LPN);
            float nr = __shfl_sync(0xffffffffu, n_l, k, LPN);
            float s  = nr * dc;
            float4 v = H[(size_t)r * LPN + lane];
            acc.x = fmaf(v.x, s, acc.x);
            acc.y = fmaf(v.y, s, acc.y);
            acc.z = fmaf(v.z, s, acc.z);
            acc.w = fmaf(v.w, s, acc.w);
        }
    }

    if (RELU_OUT) {
        acc.x = fmaxf(acc.x, 0.f); acc.y = fmaxf(acc.y, 0.f);
        acc.z = fmaxf(acc.z, 0.f); acc.w = fmaxf(acc.w, 0.f);
    }
    OUT[base] = acc;
}

__global__ void gather1_kernel(const float* __restrict__ b1) {   // g_h1 -> relu -> g_agg1
    gather_body<32, true>(g_h1, b1, g_agg1);
}

__global__ void gather2_kernel(const float* __restrict__ b2,
                               float4* __restrict__ out) {       // g_h2 -> out
    gather_body<16, false>(g_h2, b2, out);
}

// ---------------- launch -----------------------------------------------------
extern "C" void kernel_launch(void* const* d_in, const int* in_sizes, int n_in,
                              void* d_out, int out_size) {
    const float* x  = (const float*)d_in[0];
    const void*  ei = d_in[1];                     // int32 or int64, sniffed on device
    const float* W1 = (const float*)d_in[2];
    const float* b1 = (const float*)d_in[3];
    const float* W2 = (const float*)d_in[4];
    const float* b2 = (const float*)d_in[5];
    float*       out = (float*)d_out;
    (void)in_sizes; (void)n_in; (void)out_size;

    const int T = 256;
    const int MBLK = (N_NODES + 127) / 128;   // 782

    // slot 0: zero counters
    zero_kernel<<<(N_NODES + T - 1) / T, T>>>();
    // slot 1: dtype sniff
    sniff_kernel<<<1, 1>>>((const unsigned*)ei);
    // slot 2: bucket fill
    fill_kernel<<<(N_EDGES + T - 1) / T, T>>>(ei);
    // slot 3 (profiled): h1 = x @ W1  — verifies duplicated-A uplift
    gemm1_kernel<<<MBLK, 256>>>(x, W1);
    // slot 4: agg1 = relu(self+bias+edges)
    {
        long long total = (long long)N_NODES * 32;
        gather1_kernel<<<(int)((total + T - 1) / T), T>>>(b1);
    }
    // slot 5: h2 = agg1 @ W2
    gemm2_kernel<<<MBLK, 128>>>(W2);
    // slot 6: out = self+bias+edges
    {
        long long total = (long long)N_NODES * 16;
        gather2_kernel<<<(int)((total + T - 1) / T), T>>>(b2, (float4*)out);
    }
}

// round 16
// speedup vs baseline: 1.2609x; 1.2609x over previous
#include <cuda_runtime.h>
#include <cuda_fp16.h>
#include <cstdint>

#define N_NODES 100000
#define N_EDGES 1600000
#define MAXDEG  128

// ---------------- scratch: device globals (device-code references only) -----
__device__ int    g_is64;
__device__ int    g_cnt[N_NODES];
__device__ int    g_bkt[(size_t)N_NODES * MAXDEG];
__device__ __align__(16) __half g_h1[(size_t)N_NODES * 128];  // X @ W1 (fp16)
__device__ float4 g_agg1[(size_t)N_NODES * 128 / 4];          // relu(conv1) fp32
__device__ __align__(16) __half g_h2[(size_t)N_NODES * 64];   // agg1 @ W2 (fp16)

// ---------------- init: zero counters + edge dtype sniff --------------------
// int64 little-endian: odd 32-bit words are high words == 0 (ids < 2^31).
__global__ void init_kernel(const unsigned* __restrict__ ei_raw) {
    int i = blockIdx.x * blockDim.x + threadIdx.x;
    if (i < N_NODES) g_cnt[i] = 0;
    if (i == 0) {
        int zeros = 0;
#pragma unroll
        for (int k = 0; k < 64; k++)
            if (ei_raw[2 * k + 1] == 0u) zeros++;
        g_is64 = (zeros == 64) ? 1 : 0;
    }
}

__device__ __forceinline__ int edge_row(const void* ei, int e) {
    return g_is64 ? (int)((const long long*)ei)[e] : ((const int*)ei)[e];
}
__device__ __forceinline__ int edge_col(const void* ei, int e) {
    return g_is64 ? (int)((const long long*)ei)[N_EDGES + e]
                  : ((const int*)ei)[N_EDGES + e];
}

// ---------------- bucket fill -------------------------------------------------
__global__ void fill_kernel(const void* __restrict__ ei) {
    int e = blockIdx.x * blockDim.x + threadIdx.x;
    if (e < N_EDGES) {
        int r = edge_row(ei, e);
        int c = edge_col(ei, e);
        if ((unsigned)c < (unsigned)N_NODES) {
            int pos = atomicAdd(&g_cnt[c], 1);       // true degree keeps counting
            if (pos < MAXDEG) {
                int rr = ((unsigned)r < (unsigned)N_NODES) ? r : 0;
                g_bkt[(size_t)c * MAXDEG + pos] = rr;
            }
        }
    }
}

// ---------------- packed f32x2 FMA --------------------------------------------
#define FMA_F32X2(d, a, b) \
    asm("fma.rn.f32x2 %0, %1, %2, %0;" : "+l"(d) : "l"(a), "l"(b))

__device__ __forceinline__ unsigned long long pack_ff(float lo, float hi) {
    unsigned long long r;
    asm("mov.b64 %0, {%1, %2};" : "=l"(r) : "f"(lo), "f"(hi));
    return r;
}

__device__ __forceinline__ uint32_t h2_bits(float2 f) {
    __half2 h = __float22half2_rn(f);
    return *(uint32_t*)&h;
}

// ---------------- double-buffered SGEMM, FFMA2 (R13 compute, fp16 store) -----
// A [M,128] fp32 row-major, W [128,BN] fp32 row-major. H = A @ W stored fp16.
template<int BN, int NT>
__device__ __forceinline__ void gemm_body(const float* __restrict__ A,
                                          const float* __restrict__ W,
                                          __half* __restrict__ H) {
    constexpr int BM = 128, BK = 16, TM = 8, TN = 8, K = 128, KT = K / BK; // 8
    constexpr int TCOLS = BN / TN;                 // 16 (BN=128) or 8 (BN=64)
    constexpr int LA = (BM * BK) / (NT * 4);       // 2 (NT=256) or 4 (NT=128)
    constexpr int LB = (BK * BN) / (NT * 4);       // 2 (both)

    __shared__ float As[2][BK][BM];
    __shared__ float Bs[2][BK][BN];

    const int tid  = threadIdx.x;
    const int tRow = tid / TCOLS;
    const int tCol = tid % TCOLS;
    const int m0   = blockIdx.x * BM;

    unsigned long long acc2[TM][TN / 2];
#pragma unroll
    for (int i = 0; i < TM; i++)
#pragma unroll
        for (int j = 0; j < TN / 2; j++) acc2[i][j] = 0ull;

    float4 rA[LA], rB[LB];

#define G_LDG(k0)                                                             \
    {                                                                         \
        _Pragma("unroll")                                                     \
        for (int i = 0; i < LA; i++) {                                        \
            int idx = tid + i * NT;              /* float4 slot */            \
            int ar  = idx >> 2;                  /* 4 float4 per 16-f row */  \
            int ak  = (idx & 3) * 4;                                          \
            int m   = m0 + ar;                                                \
            rA[i] = (m < N_NODES)                                             \
                  ? *(const float4*)(A + (size_t)m * K + (k0) + ak)           \
                  : make_float4(0.f, 0.f, 0.f, 0.f);                          \
        }                                                                     \
        _Pragma("unroll")                                                     \
        for (int i = 0; i < LB; i++) {                                        \
            int idx = tid + i * NT;                                           \
            int bk  = idx / (BN / 4);                                         \
            int bn  = (idx % (BN / 4)) * 4;                                   \
            rB[i] = *(const float4*)(W + (size_t)((k0) + bk) * BN + bn);      \
        }                                                                     \
    }

#define G_STS(buf)                                                            \
    {                                                                         \
        _Pragma("unroll")                                                     \
        for (int i = 0; i < LA; i++) {                                        \
            int idx = tid + i * NT;                                           \
            int ar  = idx >> 2;                                               \
            int ak  = (idx & 3) * 4;                                          \
            As[buf][ak + 0][ar] = rA[i].x;                                    \
            As[buf][ak + 1][ar] = rA[i].y;                                    \
            As[buf][ak + 2][ar] = rA[i].z;                                    \
            As[buf][ak + 3][ar] = rA[i].w;                                    \
        }                                                                     \
        _Pragma("unroll")                                                     \
        for (int i = 0; i < LB; i++) {                                        \
            int idx = tid + i * NT;                                           \
            int bk  = idx / (BN / 4);                                         \
            int bn  = (idx % (BN / 4)) * 4;                                   \
            *(float4*)&Bs[buf][bk][bn] = rB[i];                               \
        }                                                                     \
    }

    G_LDG(0)
    G_STS(0)
    __syncthreads();

#pragma unroll 2
    for (int kt = 0; kt < KT; kt++) {
        const int buf = kt & 1;
        if (kt + 1 < KT) G_LDG((kt + 1) * BK)

#pragma unroll
        for (int kk = 0; kk < BK; kk++) {
            float a[TM];
#pragma unroll
            for (int i = 0; i < TM; i++) a[i] = As[buf][kk][tRow * TM + i];
            unsigned long long b2[TN / 2];
            const unsigned long long* bp =
                (const unsigned long long*)&Bs[buf][kk][tCol * TN];
#pragma unroll
            for (int j = 0; j < TN / 2; j++) b2[j] = bp[j];
#pragma unroll
            for (int i = 0; i < TM; i++) {
                unsigned long long a2 = pack_ff(a[i], a[i]);
#pragma unroll
                for (int j = 0; j < TN / 2; j++)
                    FMA_F32X2(acc2[i][j], a2, b2[j]);
            }
        }

        if (kt + 1 < KT) {
            G_STS(buf ^ 1)
            __syncthreads();
        }
    }
#undef G_LDG
#undef G_STS

    // epilogue: fp32 acc -> fp16, 8 contiguous halves = one 16B store per row
#pragma unroll
    for (int i = 0; i < TM; i++) {
        int m = m0 + tRow * TM + i;
        if (m >= N_NODES) continue;
        uint4 o;
        o.x = h2_bits(*(float2*)&acc2[i][0]);
        o.y = h2_bits(*(float2*)&acc2[i][1]);
        o.z = h2_bits(*(float2*)&acc2[i][2]);
        o.w = h2_bits(*(float2*)&acc2[i][3]);
        *(uint4*)(H + (size_t)m * BN + tCol * TN) = o;
    }
}

__global__ __launch_bounds__(256, 2)
void gemm1_kernel(const float* __restrict__ A, const float* __restrict__ W) {
    gemm_body<128, 256>(A, W, g_h1);
}

// A = g_agg1 (fp32, already relu'd by gather1)
__global__ __launch_bounds__(128, 4)
void gemm2_kernel(const float* __restrict__ W) {
    gemm_body<64, 128>((const float*)g_agg1, W, g_h2);
}

// ---------------- per-node gather over buckets (fp16 H reads) ---------------
// LPN lanes per node; each lane owns 4 columns = one uint2 (4 halves).
// OUT[c] = [relu]( H[c]*dinv[c]^2 + bias + sum_{(r,c)} dinv[r]*dinv[c]*H[r] )
template<int LPN, bool RELU_OUT>
__device__ __forceinline__ void gather_body(const uint2* __restrict__ H,
                                            const float*  __restrict__ bias,
                                            float4* __restrict__ OUT) {
    int gtid = blockIdx.x * blockDim.x + threadIdx.x;
    int node = gtid / LPN;
    int lane = gtid % LPN;
    if (node >= N_NODES) return;

    int   cnt_true = g_cnt[node];
    int   cnt      = min(cnt_true, MAXDEG);
    float dc       = rsqrtf((float)cnt_true + 1.0f);

    const size_t base = (size_t)node * LPN + lane;

    // self-loop + bias
    uint2 hu = H[base];
    float2 s01 = __half22float2(*(__half2*)&hu.x);
    float2 s23 = __half22float2(*(__half2*)&hu.y);
    float4 bi = *(const float4*)(bias + lane * 4);
    float  d2 = dc * dc;
    float4 acc = make_float4(fmaf(s01.x, d2, bi.x), fmaf(s01.y, d2, bi.y),
                             fmaf(s23.x, d2, bi.z), fmaf(s23.y, d2, bi.w));

    const int* bkt = &g_bkt[(size_t)node * MAXDEG];
    for (int j0 = 0; j0 < cnt; j0 += LPN) {
        int nb = min(LPN, cnt - j0);
        // one bucket entry per lane; dinv recomputed from counts (L2-hot)
        int   r_l = 0;
        float n_l = 0.0f;
        if (lane < nb) {
            r_l = bkt[j0 + lane];
            n_l = rsqrtf((float)g_cnt[r_l] + 1.0f);
        }
        for (int k = 0; k < nb; k++) {
            int   r  = __shfl_sync(0xffffffffu, r_l, k, LPN);
            float nr = __shfl_sync(0xffffffffu, n_l, k, LPN);
            float s  = nr * dc;
            uint2 u = H[(size_t)r * LPN + lane];
            float2 f01 = __half22float2(*(__half2*)&u.x);
            float2 f23 = __half22float2(*(__half2*)&u.y);
            acc.x = fmaf(f01.x, s, acc.x);
            acc.y = fmaf(f01.y, s, acc.y);
            acc.z = fmaf(f23.x, s, acc.z);
            acc.w = fmaf(f23.y, s, acc.w);
        }
    }

    if (RELU_OUT) {
        acc.x = fmaxf(acc.x, 0.f); acc.y = fmaxf(acc.y, 0.f);
        acc.z = fmaxf(acc.z, 0.f); acc.w = fmaxf(acc.w, 0.f);
    }
    OUT[base] = acc;
}

__global__ void gather1_kernel(const float* __restrict__ b1) {   // g_h1 -> relu -> g_agg1 (fp32)
    gather_body<32, true>((const uint2*)g_h1, b1, g_agg1);
}

__global__ void gather2_kernel(const float* __restrict__ b2,
                               float4* __restrict__ out) {       // g_h2 -> out (fp32)
    gather_body<16, false>((const uint2*)g_h2, b2, out);
}

// ---------------- launch -----------------------------------------------------
extern "C" void kernel_launch(void* const* d_in, const int* in_sizes, int n_in,
                              void* d_out, int out_size) {
    const float* x  = (const float*)d_in[0];
    const void*  ei = d_in[1];                     // int32 or int64, sniffed on device
    const float* W1 = (const float*)d_in[2];
    const float* b1 = (const float*)d_in[3];
    const float* W2 = (const float*)d_in[4];
    const float* b2 = (const float*)d_in[5];
    float*       out = (float*)d_out;
    (void)in_sizes; (void)n_in; (void)out_size;

    const int T = 256;
    const int MBLK = (N_NODES + 127) / 128;   // 782

    // slot 0: zero counters + dtype sniff
    init_kernel<<<(N_NODES + T - 1) / T, T>>>((const unsigned*)ei);
    // slot 1: bucket fill
    fill_kernel<<<(N_EDGES + T - 1) / T, T>>>(ei);
    // slot 2: h1 = x @ W1 (fp16 store)
    gemm1_kernel<<<MBLK, 256>>>(x, W1);
    // slot 3 (profiled): agg1 = relu(self+bias+edges) — verifies fp16 traffic cut
    {
        long long total = (long long)N_NODES * 32;
        gather1_kernel<<<(int)((total + T - 1) / T), T>>>(b1);
    }
    // slot 4: h2 = agg1 @ W2 (fp16 store)
    gemm2_kernel<<<MBLK, 128>>>(W2);
    // slot 5: out = self+bias+edges
    {
        long long total = (long long)N_NODES * 16;
        gather2_kernel<<<(int)((total + T - 1) / T), T>>>(b2, (float4*)out);
    }
}

// round 17
// speedup vs baseline: 1.2674x; 1.0051x over previous
#include <cuda_runtime.h>
#include <cuda_fp16.h>
#include <cstdint>

#define N_NODES 100000
#define N_EDGES 1600000
#define MAXDEG  128

// ---------------- scratch: device globals (device-code references only) -----
__device__ int    g_is64;
__device__ int    g_cnt[N_NODES];
__device__ int    g_bkt[(size_t)N_NODES * MAXDEG];
__device__ __align__(16) __half g_h1[(size_t)N_NODES * 128];  // X @ W1 (fp16)
__device__ float4 g_agg1[(size_t)N_NODES * 128 / 4];          // relu(conv1) fp32
__device__ __align__(16) __half g_h2[(size_t)N_NODES * 64];   // agg1 @ W2 (fp16)

// ---------------- init: zero counters + edge dtype sniff --------------------
// int64 little-endian: odd 32-bit words are high words == 0 (ids < 2^31).
__global__ void init_kernel(const unsigned* __restrict__ ei_raw) {
    int i = blockIdx.x * blockDim.x + threadIdx.x;
    if (i < N_NODES) g_cnt[i] = 0;
    if (i == 0) {
        int zeros = 0;
#pragma unroll
        for (int k = 0; k < 64; k++)
            if (ei_raw[2 * k + 1] == 0u) zeros++;
        g_is64 = (zeros == 64) ? 1 : 0;
    }
}

__device__ __forceinline__ int edge_row(const void* ei, int e) {
    return g_is64 ? (int)((const long long*)ei)[e] : ((const int*)ei)[e];
}
__device__ __forceinline__ int edge_col(const void* ei, int e) {
    return g_is64 ? (int)((const long long*)ei)[N_EDGES + e]
                  : ((const int*)ei)[N_EDGES + e];
}

// ---------------- bucket fill -------------------------------------------------
__global__ void fill_kernel(const void* __restrict__ ei) {
    int e = blockIdx.x * blockDim.x + threadIdx.x;
    if (e < N_EDGES) {
        int r = edge_row(ei, e);
        int c = edge_col(ei, e);
        if ((unsigned)c < (unsigned)N_NODES) {
            int pos = atomicAdd(&g_cnt[c], 1);       // true degree keeps counting
            if (pos < MAXDEG) {
                int rr = ((unsigned)r < (unsigned)N_NODES) ? r : 0;
                g_bkt[(size_t)c * MAXDEG + pos] = rr;
            }
        }
    }
}

// ---------------- packed f32x2 FMA --------------------------------------------
#define FMA_F32X2(d, a, b) \
    asm("fma.rn.f32x2 %0, %1, %2, %0;" : "+l"(d) : "l"(a), "l"(b))

__device__ __forceinline__ unsigned long long pack_ff(float lo, float hi) {
    unsigned long long r;
    asm("mov.b64 %0, {%1, %2};" : "=l"(r) : "f"(lo), "f"(hi));
    return r;
}

__device__ __forceinline__ uint32_t h2_bits(float2 f) {
    __half2 h = __float22half2_rn(f);
    return *(uint32_t*)&h;
}

// ---------------- double-buffered SGEMM, FFMA2 (R13 compute, fp16 store) -----
// A [M,128] fp32 row-major, W [128,BN] fp32 row-major. H = A @ W stored fp16.
template<int BN, int NT>
__device__ __forceinline__ void gemm_body(const float* __restrict__ A,
                                          const float* __restrict__ W,
                                          __half* __restrict__ H) {
    constexpr int BM = 128, BK = 16, TM = 8, TN = 8, K = 128, KT = K / BK; // 8
    constexpr int TCOLS = BN / TN;                 // 16 (BN=128) or 8 (BN=64)
    constexpr int LA = (BM * BK) / (NT * 4);       // 2 (NT=256) or 4 (NT=128)
    constexpr int LB = (BK * BN) / (NT * 4);       // 2 (both)

    __shared__ float As[2][BK][BM];
    __shared__ float Bs[2][BK][BN];

    const int tid  = threadIdx.x;
    const int tRow = tid / TCOLS;
    const int tCol = tid % TCOLS;
    const int m0   = blockIdx.x * BM;

    unsigned long long acc2[TM][TN / 2];
#pragma unroll
    for (int i = 0; i < TM; i++)
#pragma unroll
        for (int j = 0; j < TN / 2; j++) acc2[i][j] = 0ull;

    float4 rA[LA], rB[LB];

#define G_LDG(k0)                                                             \
    {                                                                         \
        _Pragma("unroll")                                                     \
        for (int i = 0; i < LA; i++) {                                        \
            int idx = tid + i * NT;              /* float4 slot */            \
            int ar  = idx >> 2;                  /* 4 float4 per 16-f row */  \
            int ak  = (idx & 3) * 4;                                          \
            int m   = m0 + ar;                                                \
            rA[i] = (m < N_NODES)                                             \
                  ? *(const float4*)(A + (size_t)m * K + (k0) + ak)           \
                  : make_float4(0.f, 0.f, 0.f, 0.f);                          \
        }                                                                     \
        _Pragma("unroll")                                                     \
        for (int i = 0; i < LB; i++) {                                        \
            int idx = tid + i * NT;                                           \
            int bk  = idx / (BN / 4);                                         \
            int bn  = (idx % (BN / 4)) * 4;                                   \
            rB[i] = *(const float4*)(W + (size_t)((k0) + bk) * BN + bn);      \
        }                                                                     \
    }

#define G_STS(buf)                                                            \
    {                                                                         \
        _Pragma("unroll")                                                     \
        for (int i = 0; i < LA; i++) {                                        \
            int idx = tid + i * NT;                                           \
            int ar  = idx >> 2;                                               \
            int ak  = (idx & 3) * 4;                                          \
            As[buf][ak + 0][ar] = rA[i].x;                                    \
            As[buf][ak + 1][ar] = rA[i].y;                                    \
            As[buf][ak + 2][ar] = rA[i].z;                                    \
            As[buf][ak + 3][ar] = rA[i].w;                                    \
        }                                                                     \
        _Pragma("unroll")                                                     \
        for (int i = 0; i < LB; i++) {                                        \
            int idx = tid + i * NT;                                           \
            int bk  = idx / (BN / 4);                                         \
            int bn  = (idx % (BN / 4)) * 4;                                   \
            *(float4*)&Bs[buf][bk][bn] = rB[i];                               \
        }                                                                     \
    }

    G_LDG(0)
    G_STS(0)
    __syncthreads();

#pragma unroll 2
    for (int kt = 0; kt < KT; kt++) {
        const int buf = kt & 1;
        if (kt + 1 < KT) G_LDG((kt + 1) * BK)

#pragma unroll
        for (int kk = 0; kk < BK; kk++) {
            float a[TM];
#pragma unroll
            for (int i = 0; i < TM; i++) a[i] = As[buf][kk][tRow * TM + i];
            unsigned long long b2[TN / 2];
            const unsigned long long* bp =
                (const unsigned long long*)&Bs[buf][kk][tCol * TN];
#pragma unroll
            for (int j = 0; j < TN / 2; j++) b2[j] = bp[j];
#pragma unroll
            for (int i = 0; i < TM; i++) {
                unsigned long long a2 = pack_ff(a[i], a[i]);
#pragma unroll
                for (int j = 0; j < TN / 2; j++)
                    FMA_F32X2(acc2[i][j], a2, b2[j]);
            }
        }

        if (kt + 1 < KT) {
            G_STS(buf ^ 1)
            __syncthreads();
        }
    }
#undef G_LDG
#undef G_STS

    // epilogue: fp32 acc -> fp16, 8 contiguous halves = one 16B store per row
#pragma unroll
    for (int i = 0; i < TM; i++) {
        int m = m0 + tRow * TM + i;
        if (m >= N_NODES) continue;
        uint4 o;
        o.x = h2_bits(*(float2*)&acc2[i][0]);
        o.y = h2_bits(*(float2*)&acc2[i][1]);
        o.z = h2_bits(*(float2*)&acc2[i][2]);
        o.w = h2_bits(*(float2*)&acc2[i][3]);
        *(uint4*)(H + (size_t)m * BN + tCol * TN) = o;
    }
}

__global__ __launch_bounds__(256, 2)
void gemm1_kernel(const float* __restrict__ A, const float* __restrict__ W) {
    gemm_body<128, 256>(A, W, g_h1);
}

// A = g_agg1 (fp32, already relu'd by gather1)
__global__ __launch_bounds__(128, 4)
void gemm2_kernel(const float* __restrict__ W) {
    gemm_body<64, 128>((const float*)g_agg1, W, g_h2);
}

// ---------------- per-node gather over buckets (fp16 H reads) ---------------
// LPN lanes per node; each lane owns 4 columns = one uint2 (4 halves).
// OUT[c] = [relu]( H[c]*dinv[c]^2 + bias + sum_{(r,c)} dinv[r]*dinv[c]*H[r] )
template<int LPN, bool RELU_OUT>
__device__ __forceinline__ void gather_body(const uint2* __restrict__ H,
                                            const float*  __restrict__ bias,
                                            float4* __restrict__ OUT) {
    int gtid = blockIdx.x * blockDim.x + threadIdx.x;
    int node = gtid / LPN;
    int lane = gtid % LPN;
    if (node >= N_NODES) return;

    int   cnt_true = g_cnt[node];
    int   cnt      = min(cnt_true, MAXDEG);
    float dc       = rsqrtf((float)cnt_true + 1.0f);

    const size_t base = (size_t)node * LPN + lane;

    // self-loop + bias
    uint2 hu = H[base];
    float2 s01 = __half22float2(*(__half2*)&hu.x);
    float2 s23 = __half22float2(*(__half2*)&hu.y);
    float4 bi = *(const float4*)(bias + lane * 4);
    float  d2 = dc * dc;
    float4 acc = make_float4(fmaf(s01.x, d2, bi.x), fmaf(s01.y, d2, bi.y),
                             fmaf(s23.x, d2, bi.z), fmaf(s23.y, d2, bi.w));

    const int* bkt = &g_bkt[(size_t)node * MAXDEG];
    for (int j0 = 0; j0 < cnt; j0 += LPN) {
        int nb = min(LPN, cnt - j0);
        // one bucket entry per lane; dinv recomputed from counts (L2-hot)
        int   r_l = 0;
        float n_l = 0.0f;
        if (lane < nb) {
            r_l = bkt[j0 + lane];
            n_l = rsqrtf((float)g_cnt[r_l] + 1.0f);
        }
        for (int k = 0; k < nb; k++) {
            int   r  = __shfl_sync(0xffffffffu, r_l, k, LPN);
            float nr = __shfl_sync(0xffffffffu, n_l, k, LPN);
            float s  = nr * dc;
            uint2 u = H[(size_t)r * LPN + lane];
            float2 f01 = __half22float2(*(__half2*)&u.x);
            float2 f23 = __half22float2(*(__half2*)&u.y);
            acc.x = fmaf(f01.x, s, acc.x);
            acc.y = fmaf(f01.y, s, acc.y);
            acc.z = fmaf(f23.x, s, acc.z);
            acc.w = fmaf(f23.y, s, acc.w);
        }
    }

    if (RELU_OUT) {
        acc.x = fmaxf(acc.x, 0.f); acc.y = fmaxf(acc.y, 0.f);
        acc.z = fmaxf(acc.z, 0.f); acc.w = fmaxf(acc.w, 0.f);
    }
    OUT[base] = acc;
}

__global__ void gather1_kernel(const float* __restrict__ b1) {   // g_h1 -> relu -> g_agg1 (fp32)
    gather_body<32, true>((const uint2*)g_h1, b1, g_agg1);
}

__global__ void gather2_kernel(const float* __restrict__ b2,
                               float4* __restrict__ out) {       // g_h2 -> out (fp32)
    gather_body<16, false>((const uint2*)g_h2, b2, out);
}

// ---------------- launch: fork-join overlap of CSR build with gemm1 ---------
extern "C" void kernel_launch(void* const* d_in, const int* in_sizes, int n_in,
                              void* d_out, int out_size) {
    const float* x  = (const float*)d_in[0];
    const void*  ei = d_in[1];                     // int32 or int64, sniffed on device
    const float* W1 = (const float*)d_in[2];
    const float* b1 = (const float*)d_in[3];
    const float* W2 = (const float*)d_in[4];
    const float* b2 = (const float*)d_in[5];
    float*       out = (float*)d_out;
    (void)in_sizes; (void)n_in; (void)out_size;

    const int T = 256;
    const int MBLK = (N_NODES + 127) / 128;   // 782

    // Fork a side stream for the CSR build (init+fill), which is independent
    // of gemm1. Objects are intentionally NOT destroyed here: they may be
    // referenced by an in-progress graph capture (destroying then is illegal).
    // kernel_launch is invoked only a handful of times per process, so the
    // leak is bounded and allocates no device memory.
    cudaStream_t s2;
    cudaEvent_t  eFork, eJoin;
    cudaStreamCreateWithFlags(&s2, cudaStreamNonBlocking);
    cudaEventCreateWithFlags(&eFork, cudaEventDisableTiming);
    cudaEventCreateWithFlags(&eJoin, cudaEventDisableTiming);

    // fork: side stream joins the capture via event dependency
    cudaEventRecord(eFork, 0);
    cudaStreamWaitEvent(s2, eFork, 0);

    // side stream: CSR build (init -> fill)
    init_kernel<<<(N_NODES + T - 1) / T, T, 0, s2>>>((const unsigned*)ei);
    fill_kernel<<<(N_EDGES + T - 1) / T, T, 0, s2>>>(ei);
    cudaEventRecord(eJoin, s2);

    // main stream: gemm1 runs concurrently with the CSR build
    gemm1_kernel<<<MBLK, 256>>>(x, W1);

    // join: gather1 needs both gemm1 (main) and fill (side)
    cudaStreamWaitEvent(0, eJoin, 0);

    {
        long long total = (long long)N_NODES * 32;
        gather1_kernel<<<(int)((total + T - 1) / T), T>>>(b1);
    }
    gemm2_kernel<<<MBLK, 128>>>(W2);
    {
        long long total = (long long)N_NODES * 16;
        gather2_kernel<<<(int)((total + T - 1) / T), T>>>(b2, (float4*)out);
    }
}